// round 14
// baseline (speedup 1.0000x reference)
#include <cuda_runtime.h>
#include <cuda_fp16.h>
#include <cstdint>

// ---------------- scratch (allocation-free: __device__ globals) ----------------
#define T_TOK 8192
__device__ __half g_qa [T_TOK*1536];   // wq_a output (fp16)
__device__ __half g_qah[T_TOK*1536];   // rmsnorm(qa) in fp16
__device__ __half g_q  [T_TOK*3072];   // wq_b output (fp16, attention input)
__device__ float  g_kva[T_TOK*576];    // wkv_a output (fp32)
__device__ __half g_kvn[T_TOK*512];    // normalized kv latent (fp16)
__device__ float  g_kpe[T_TOK*64];     // roped k_pe
__device__ __half g_kv [T_TOK*4096];   // wkv_b output (fp16)
__device__ __half g_ao [T_TOK*2048];   // attention output (fp16)
__device__ __half g_xh [T_TOK*2048];   // x in fp16
__device__ __half g_wh [15335424];     // all 5 weight matrices in fp16

#define WQA_OFF   0
#define WQB_OFF   3145728
#define WKVA_OFF  7864320
#define WKVB_OFF  9043968
#define WO_OFF    11141120

// ---------------- PTX helpers (arch-generic: sm_80+) ----------------
__device__ __forceinline__ void cp_async16(void* dst, const void* src) {
    unsigned s = (unsigned)__cvta_generic_to_shared(dst);
    asm volatile("cp.async.cg.shared.global [%0], [%1], 16;\n" :: "r"(s), "l"(src));
}
__device__ __forceinline__ void cp_commit() { asm volatile("cp.async.commit_group;\n"); }
template<int N> __device__ __forceinline__ void cp_wait() {
    asm volatile("cp.async.wait_group %0;\n" :: "n"(N));
}
__device__ __forceinline__ void mma16816(float* d, const uint32_t* a, const uint32_t* b) {
    asm volatile(
        "mma.sync.aligned.m16n8k16.row.col.f32.f16.f16.f32 "
        "{%0,%1,%2,%3}, {%4,%5,%6,%7}, {%8,%9}, {%0,%1,%2,%3};"
        : "+f"(d[0]), "+f"(d[1]), "+f"(d[2]), "+f"(d[3])
        : "r"(a[0]), "r"(a[1]), "r"(a[2]), "r"(a[3]), "r"(b[0]), "r"(b[1]));
}
__device__ __forceinline__ void ldsm_x4(uint32_t a, uint32_t* r) {
    asm volatile("ldmatrix.sync.aligned.m8n8.x4.shared.b16 {%0,%1,%2,%3}, [%4];"
        : "=r"(r[0]), "=r"(r[1]), "=r"(r[2]), "=r"(r[3]) : "r"(a));
}
// epilogue store: fp32 or fp16 output via overload
__device__ __forceinline__ void store2(float* p, float a, float b) {
    *(float2*)p = make_float2(a, b);
}
__device__ __forceinline__ void store2(__half* p, float a, float b) {
    *(__half2*)p = __floats2half2_rn(a, b);
}

// ---------------- fp16 mma.sync GEMM: C[M,N] = A[M,K] @ W[N,K]^T + bias[N] ---
// BM=BN=128, BK=64, 256 threads (8 warps 2x4), warp tile 64x32 (4x4 m16n8k16).
// fp32 accumulate; OutT = float or __half. Row stride 72 halves (144B) keeps
// every 8-row ldmatrix phase conflict-free. 3-stage cp.async pipeline, one
// barrier per K-tile; fragment double-buffering across the 4 k16 sub-steps.
#define ROWB 144                          // bytes per smem row (72 halves)
#define TILE_BYTES (128 * ROWB)           // 18432 B per tile (A or B)
#define STG_BYTES (2 * TILE_BYTES)        // 36864 B per stage
#define GEMM_SMEM (3 * STG_BYTES + 512)   // 111104 B

template<typename OutT>
__global__ __launch_bounds__(256, 2) void gemm_mma(
    const __half* __restrict__ A, const __half* __restrict__ W,
    const float* __restrict__ bias, OutT* __restrict__ C,
    int M, int N, int K)
{
    extern __shared__ char smem[];
    float* sBias = (float*)(smem + 3 * STG_BYTES);
    const uint32_t smem_u = (uint32_t)__cvta_generic_to_shared(smem);

    const int tid = threadIdx.x, warp = tid >> 5, lane = tid & 31;
    const int gid = lane >> 2, tig = lane & 3;
    const int bm = blockIdx.y * 128, bn = blockIdx.x * 128;
    const int wm = (warp >> 2) * 64, wn = (warp & 3) * 32;
    const int KT = K / 64;

    if (tid < 128) {
        int c = bn + tid;
        sBias[tid] = (c < N) ? bias[c] : 0.0f;
    }

    float acc[4][4][4];
#pragma unroll
    for (int i = 0; i < 4; i++)
#pragma unroll
        for (int j = 0; j < 4; j++)
#pragma unroll
            for (int r = 0; r < 4; r++) acc[i][j][r] = 0.0f;

    const int lrow = tid >> 3, lc16 = tid & 7;
    auto load_stage = [&](int kt) {
        char* st = smem + (kt % 3) * STG_BYTES;
        const int k0 = kt * 64;
#pragma unroll
        for (int i = 0; i < 4; i++) {
            const int row = lrow + i * 32;
            cp_async16(st + row * ROWB + lc16 * 16,
                       A + (size_t)(bm + row) * K + k0 + lc16 * 8);
            int rB = bn + row; if (rB >= N) rB = N - 1;   // clamp; junk cols never stored
            cp_async16(st + TILE_BYTES + row * ROWB + lc16 * 16,
                       W + (size_t)rB * K + k0 + lc16 * 8);
        }
        cp_commit();
    };

    const uint32_t aOff = (uint32_t)(wm + (lane & 15)) * ROWB + ((lane >> 4) << 4);
    const uint32_t bOff = TILE_BYTES
        + (uint32_t)(wn + ((lane >> 4) << 3) + (lane & 7)) * ROWB + (((lane >> 3) & 1) << 4);

    load_stage(0);
    load_stage(1);

    for (int kt = 0; kt < KT; kt++) {
        if (kt + 1 < KT) cp_wait<1>(); else cp_wait<0>();
        __syncthreads();                       // stage kt visible; stage (kt+2)%3 free
        if (kt + 2 < KT) load_stage(kt + 2);

        const uint32_t stg = smem_u + (kt % 3) * STG_BYTES;
        const uint32_t aB = stg + aOff;
        const uint32_t bB = stg + bOff;

        uint32_t Af[2][4][4], Bq[2][2][4];
#pragma unroll
        for (int i = 0; i < 4; i++) ldsm_x4(aB + (uint32_t)(i * 16 * ROWB), Af[0][i]);
#pragma unroll
        for (int p = 0; p < 2; p++) ldsm_x4(bB + (uint32_t)(p * 16 * ROWB), Bq[0][p]);

#pragma unroll
        for (int kk = 0; kk < 4; kk++) {       // 4 x k16 sub-steps (32B each)
            const int cur = kk & 1;
            if (kk < 3) {   // prefetch kk+1 fragments while cur's MMAs drain
                const uint32_t ko = (uint32_t)(kk + 1) * 32;
#pragma unroll
                for (int i = 0; i < 4; i++)
                    ldsm_x4(aB + ko + (uint32_t)(i * 16 * ROWB), Af[cur ^ 1][i]);
#pragma unroll
                for (int p = 0; p < 2; p++)
                    ldsm_x4(bB + ko + (uint32_t)(p * 16 * ROWB), Bq[cur ^ 1][p]);
            }
#pragma unroll
            for (int i = 0; i < 4; i++)
#pragma unroll
                for (int j = 0; j < 4; j++)
                    mma16816(acc[i][j], Af[cur][i], &Bq[cur][j >> 1][(j & 1) * 2]);
        }
    }

    // epilogue: direct 2-wide stores (+bias)
#pragma unroll
    for (int i = 0; i < 4; i++) {
        const int r0 = bm + wm + i * 16 + gid;
        const int r1 = r0 + 8;
#pragma unroll
        for (int j = 0; j < 4; j++) {
            const int c = wn + j * 8 + tig * 2;
            if (bn + c < N) {
                const float b0 = sBias[c], b1 = sBias[c + 1];
                store2(C + (size_t)r0 * N + bn + c, acc[i][j][0] + b0, acc[i][j][1] + b1);
                store2(C + (size_t)r1 * N + bn + c, acc[i][j][2] + b0, acc[i][j][3] + b1);
            }
        }
    }
}

// ---------------- fp32 -> fp16 rounding prepass (float4 in, 8B out) ----------
__global__ __launch_bounds__(256) void round_fp16_k(
    const float* __restrict__ in, __half* __restrict__ out, int n)
{
    int i = (blockIdx.x * 256 + threadIdx.x) * 4;
    if (i < n) {
        float4 v = *(const float4*)(in + i);
        *(__half2*)(out + i)     = __floats2half2_rn(v.x, v.y);
        *(__half2*)(out + i + 2) = __floats2half2_rn(v.z, v.w);
    }
}

// ---------------- RMSNorm: fp16 in -> fp16 out (fp32 math) ----------------
__global__ __launch_bounds__(256) void rmsnorm_fp16(
    const __half* __restrict__ data, const float* __restrict__ w,
    __half* __restrict__ outp, int W)
{
    const int t = blockIdx.x, tid = threadIdx.x;
    const __half* p = data + (size_t)t * W;
    __half* o = outp + (size_t)t * W;
    const int W2 = W >> 1;
    float ss = 0.f;
    for (int i = tid; i < W2; i += 256) {
        float2 v = __half22float2(((const __half2*)p)[i]);
        ss += v.x * v.x + v.y * v.y;
    }
    __shared__ float red[256];
    red[tid] = ss; __syncthreads();
    for (int w2 = 128; w2 > 0; w2 >>= 1) {
        if (tid < w2) red[tid] += red[tid + w2];
        __syncthreads();
    }
    const float inv = rsqrtf(red[0] / (float)W + 1.1920929e-7f);
    for (int i = tid; i < W2; i += 256) {
        float2 v = __half22float2(((const __half2*)p)[i]);
        const float2 g = ((const float2*)w)[i];
        *(__half2*)(o + 2 * i) = __floats2half2_rn(v.x * inv * g.x, v.y * inv * g.y);
    }
}

// ---------------- kv_a post-process: rmsnorm(512)->fp16 + rope(last 64) ------
__global__ __launch_bounds__(128) void kv_prep(
    const float* __restrict__ kva, const float* __restrict__ knw,
    const float* __restrict__ cosb, const float* __restrict__ sinb,
    __half* __restrict__ kvn, float* __restrict__ kpe, int S)
{
    const int t = blockIdx.x, tid = threadIdx.x;
    const int s = t % S;
    const float* src = kva + (size_t)t * 576;
    float ss = 0.f;
    for (int i = tid; i < 512; i += 128) { float v = src[i]; ss += v * v; }
    __shared__ float red[128];
    red[tid] = ss; __syncthreads();
    for (int w2 = 64; w2 > 0; w2 >>= 1) {
        if (tid < w2) red[tid] += red[tid + w2];
        __syncthreads();
    }
    const float inv = rsqrtf(red[0] / 512.0f + 1.1920929e-7f);
    for (int i = tid; i < 512; i += 128)
        kvn[(size_t)t * 512 + i] = __float2half_rn(src[i] * inv * knw[i]);
    if (tid < 32) {
        const int j = tid;
        const float c = cosb[s * 32 + j], sn = sinb[s * 32 + j];
        const float x0 = src[512 + 2 * j], x1 = src[512 + 2 * j + 1];
        kpe[(size_t)t * 64 + 2 * j]     = x0 * c  - x1 * sn;
        kpe[(size_t)t * 64 + 2 * j + 1] = x0 * sn + x1 * c;
    }
}

// ---------------- per-token attention (fp16 in, fp16 out, fp32 math) ---------
#define ATT_SCALE 0.07216878364870322f  // (128+64)^-0.5
__global__ __launch_bounds__(128) void attn_kernel(
    const __half* __restrict__ q, const __half* __restrict__ kv,
    const float* __restrict__ kpe, const float* __restrict__ cosb,
    const float* __restrict__ sinb, __half* __restrict__ out, int S, int toff)
{
    const int t = blockIdx.x, tid = threadIdx.x;
    const int s = (t + toff) % S;
    __shared__ float qs[3072];
    __shared__ float kvs[16 * 260];
    __shared__ float kp[64];
    __shared__ float sc[16][17];

    const __half* qg = q + (size_t)t * 3072;
    for (int i = tid; i < 1536; i += 128) {
        float2 f = __half22float2(((const __half2*)qg)[i]);
        qs[2 * i] = f.x; qs[2 * i + 1] = f.y;
    }
    const __half* kvg = kv + (size_t)t * 4096;
    for (int i = tid; i < 2048; i += 128) {
        const int g = i >> 7, c = i & 127;
        float2 f = __half22float2(((const __half2*)kvg)[i]);
        kvs[g * 260 + 2 * c] = f.x; kvs[g * 260 + 2 * c + 1] = f.y;
    }
    if (tid < 16) ((float4*)kp)[tid] = ((const float4*)(kpe + (size_t)t * 64))[tid];
    __syncthreads();

    for (int p = tid; p < 512; p += 128) {
        const int h = p >> 5, j = p & 31;
        const float c = cosb[s * 32 + j], sn = sinb[s * 32 + j];
        const int i0 = h * 192 + 128 + 2 * j;
        const float x0 = qs[i0], x1 = qs[i0 + 1];
        qs[i0]     = x0 * c  - x1 * sn;
        qs[i0 + 1] = x0 * sn + x1 * c;
    }
    __syncthreads();

    {
        const int h = tid >> 3, g0 = tid & 7, g1 = g0 + 8;
        const float* qh = &qs[h * 192];
        const float* k0 = &kvs[g0 * 260];
        const float* k1 = &kvs[g1 * 260];
        float a0 = 0.f, a1 = 0.f;
#pragma unroll 8
        for (int d = 0; d < 128; d++) { const float qd = qh[d]; a0 += qd * k0[d]; a1 += qd * k1[d]; }
        float pe = 0.f;
        const float* qp = &qs[h * 192 + 128];
#pragma unroll 8
        for (int d = 0; d < 64; d++) pe += qp[d] * kp[d];
        sc[h][g0] = (a0 + pe) * ATT_SCALE;
        sc[h][g1] = (a1 + pe) * ATT_SCALE;
    }
    __syncthreads();

    if (tid < 16) {
        float m = -1e30f;
#pragma unroll
        for (int g = 0; g < 16; g++) m = fmaxf(m, sc[tid][g]);
        float sum = 0.f;
#pragma unroll
        for (int g = 0; g < 16; g++) { const float e = expf(sc[tid][g] - m); sc[tid][g] = e; sum += e; }
        const float r = 1.f / sum;
#pragma unroll
        for (int g = 0; g < 16; g++) sc[tid][g] *= r;
    }
    __syncthreads();

    for (int o = tid; o < 2048; o += 128) {
        const int h = o >> 7, d = o & 127;
        float acc = 0.f;
#pragma unroll
        for (int g = 0; g < 16; g++) acc += sc[h][g] * kvs[g * 260 + 128 + d];
        out[(size_t)t * 2048 + o] = __float2half_rn(acc);
    }
}

// ---------------- host launcher (dual-stream, token-chunked tail) ------------
template<typename OutT>
static inline void launch_gemm_s(cudaStream_t st, const __half* A, const __half* W,
                                 const float* bias, OutT* C, int M, int N, int K)
{
    dim3 grid((N + 127) / 128, M / 128);
    gemm_mma<OutT><<<grid, 256, GEMM_SMEM, st>>>(A, W, bias, C, M, N, K);
}
static inline void launch_round_s(cudaStream_t st, const float* in, __half* out, int n)
{
    round_fp16_k<<<(n / 4 + 255) / 256, 256, 0, st>>>(in, out, n);
}

extern "C" void kernel_launch(void* const* d_in, const int* in_sizes, int n_in,
                              void* d_out, int out_size)
{
    const float* x     = (const float*)d_in[0];
    const float* fcos  = (const float*)d_in[1];
    const float* fsin  = (const float*)d_in[2];
    const float* wqa   = (const float*)d_in[3];
    const float* wqab  = (const float*)d_in[4];
    const float* qnw   = (const float*)d_in[5];
    const float* wqb   = (const float*)d_in[6];
    const float* wqbb  = (const float*)d_in[7];
    const float* wkva  = (const float*)d_in[8];
    const float* wkvab = (const float*)d_in[9];
    const float* kvnw  = (const float*)d_in[10];
    const float* wkvb  = (const float*)d_in[11];
    const float* wkvbb = (const float*)d_in[12];
    const float* wo    = (const float*)d_in[13];
    const float* wob   = (const float*)d_in[14];
    float* out = (float*)d_out;

    const int T = in_sizes[0] / 2048;   // B*S tokens (8192)
    const int S = in_sizes[1] / 32;     // 2048
    const int T2 = T / 2;

    float *kva, *kpe;
    __half *qa, *qah, *qq, *kvn, *kv, *ao, *xh, *wh;
    cudaGetSymbolAddress((void**)&qa,  g_qa);
    cudaGetSymbolAddress((void**)&qah, g_qah);
    cudaGetSymbolAddress((void**)&qq,  g_q);
    cudaGetSymbolAddress((void**)&kva, g_kva);
    cudaGetSymbolAddress((void**)&kvn, g_kvn);
    cudaGetSymbolAddress((void**)&kpe, g_kpe);
    cudaGetSymbolAddress((void**)&kv,  g_kv);
    cudaGetSymbolAddress((void**)&ao,  g_ao);
    cudaGetSymbolAddress((void**)&xh,  g_xh);
    cudaGetSymbolAddress((void**)&wh,  g_wh);

    cudaFuncSetAttribute(gemm_mma<float>,  cudaFuncAttributeMaxDynamicSharedMemorySize, GEMM_SMEM);
    cudaFuncSetAttribute(gemm_mma<__half>, cudaFuncAttributeMaxDynamicSharedMemorySize, GEMM_SMEM);

    // Host-side stream/event handles, created once (uncaptured correctness
    // call); identical DAG recorded on every call -> identical graph.
    static cudaStream_t s1 = nullptr;
    static cudaEvent_t eFork, eX, eWQB, eKV, eQ0, eS1;
    if (s1 == nullptr) {
        cudaStreamCreateWithFlags(&s1, cudaStreamNonBlocking);
        cudaEventCreateWithFlags(&eFork, cudaEventDisableTiming);
        cudaEventCreateWithFlags(&eX,    cudaEventDisableTiming);
        cudaEventCreateWithFlags(&eWQB,  cudaEventDisableTiming);
        cudaEventCreateWithFlags(&eKV,   cudaEventDisableTiming);
        cudaEventCreateWithFlags(&eQ0,   cudaEventDisableTiming);
        cudaEventCreateWithFlags(&eS1,   cudaEventDisableTiming);
    }
    cudaStream_t d = 0;                 // capture-origin (legacy default) stream

    // fork s1 off the capture stream
    cudaEventRecord(eFork, d);
    cudaStreamWaitEvent(s1, eFork, 0);

    // ---- default stream: q path ----
    launch_round_s(d, x, xh, T * 2048);
    cudaEventRecord(eX, d);                               // xh ready
    launch_round_s(d, wqa, wh + WQA_OFF, 1536 * 2048);
    launch_gemm_s(d, xh, wh + WQA_OFF, wqab, qa, T, 1536, 2048);
    rmsnorm_fp16<<<T, 256, 0, d>>>(qa, qnw, qah, 1536);

    // ---- s1: remaining weight rounds + kv path ----
    launch_round_s(s1, wqb, wh + WQB_OFF, 3072 * 1536);
    cudaEventRecord(eWQB, s1);                            // wqb(h) ready
    launch_round_s(s1, wkva, wh + WKVA_OFF, 576 * 2048);
    launch_round_s(s1, wkvb, wh + WKVB_OFF, 4096 * 512);
    launch_round_s(s1, wo,   wh + WO_OFF,   2048 * 2048);
    cudaStreamWaitEvent(s1, eX, 0);                       // needs xh
    launch_gemm_s(s1, xh, wh + WKVA_OFF, wkvab, kva, T, 576, 2048);
    kv_prep<<<T, 128, 0, s1>>>(kva, kvnw, fcos, fsin, kvn, kpe, S);
    launch_gemm_s(s1, kvn, wh + WKVB_OFF, wkvbb, kv, T, 4096, 512);
    cudaEventRecord(eKV, s1);                             // kv ready (incl. wo round)

    // ---- default stream: wq_b in two token-halves ----
    cudaStreamWaitEvent(d, eWQB, 0);
    launch_gemm_s(d, qah, wh + WQB_OFF, wqbb, qq, T2, 3072, 1536);
    cudaEventRecord(eQ0, d);                              // qq half-0 ready
    launch_gemm_s(d, qah + (size_t)T2 * 1536, wh + WQB_OFF, wqbb,
                  qq + (size_t)T2 * 3072, T2, 3072, 1536);

    // ---- s1: attn + wo on token half-0 (overlaps wq_b half-1 on d) ----
    cudaStreamWaitEvent(s1, eQ0, 0);
    attn_kernel<<<T2, 128, 0, s1>>>(qq, kv, kpe, fcos, fsin, ao, S, 0);
    launch_gemm_s(s1, ao, wh + WO_OFF, wob, out, T2, 2048, 2048);
    cudaEventRecord(eS1, s1);

    // ---- default stream: attn + wo on token half-1, then join ----
    cudaStreamWaitEvent(d, eKV, 0);
    attn_kernel<<<T2, 128, 0, d>>>(qq + (size_t)T2 * 3072, kv + (size_t)T2 * 4096,
                                   kpe + (size_t)T2 * 64, fcos, fsin,
                                   ao + (size_t)T2 * 2048, S, T2);
    launch_gemm_s(d, ao + (size_t)T2 * 2048, wh + WO_OFF, wob,
                  out + (size_t)T2 * 2048, T2, 2048, 2048);
    cudaStreamWaitEvent(d, eS1, 0);                       // join s1
}

// round 15
// speedup vs baseline: 1.0000x; 1.0000x over previous
#include <cuda_runtime.h>
#include <cuda_fp16.h>
#include <cstdint>

// ---------------- scratch (allocation-free: __device__ globals) ----------------
#define T_TOK 8192
__device__ float  g_qa [T_TOK*1536];   // wq_a output (fp32)
__device__ __half g_qah[T_TOK*1536];   // rmsnorm(qa) in fp16
__device__ __half g_q  [T_TOK*3072];   // wq_b output (fp16, attention input)
__device__ float  g_kva[T_TOK*576];    // wkv_a output (fp32)
__device__ __half g_kvn[T_TOK*512];    // normalized kv latent (fp16)
__device__ float  g_kpe[T_TOK*64];     // roped k_pe
__device__ __half g_kv [T_TOK*4096];   // wkv_b output (fp16)
__device__ __half g_ao [T_TOK*2048];   // attention output (fp16)
__device__ __half g_xh [T_TOK*2048];   // x in fp16
__device__ __half g_wh [15335424];     // all 5 weight matrices in fp16

#define WQA_OFF   0
#define WQB_OFF   3145728
#define WKVA_OFF  7864320
#define WKVB_OFF  9043968
#define WO_OFF    11141120

// ---------------- PTX helpers (arch-generic: sm_80+) ----------------
__device__ __forceinline__ void cp_async16(void* dst, const void* src) {
    unsigned s = (unsigned)__cvta_generic_to_shared(dst);
    asm volatile("cp.async.cg.shared.global [%0], [%1], 16;\n" :: "r"(s), "l"(src));
}
__device__ __forceinline__ void cp_commit() { asm volatile("cp.async.commit_group;\n"); }
template<int N> __device__ __forceinline__ void cp_wait() {
    asm volatile("cp.async.wait_group %0;\n" :: "n"(N));
}
__device__ __forceinline__ void mma16816(float* d, const uint32_t* a, const uint32_t* b) {
    asm volatile(
        "mma.sync.aligned.m16n8k16.row.col.f32.f16.f16.f32 "
        "{%0,%1,%2,%3}, {%4,%5,%6,%7}, {%8,%9}, {%0,%1,%2,%3};"
        : "+f"(d[0]), "+f"(d[1]), "+f"(d[2]), "+f"(d[3])
        : "r"(a[0]), "r"(a[1]), "r"(a[2]), "r"(a[3]), "r"(b[0]), "r"(b[1]));
}
__device__ __forceinline__ void ldsm_x4(uint32_t a, uint32_t* r) {
    asm volatile("ldmatrix.sync.aligned.m8n8.x4.shared.b16 {%0,%1,%2,%3}, [%4];"
        : "=r"(r[0]), "=r"(r[1]), "=r"(r[2]), "=r"(r[3]) : "r"(a));
}
// epilogue store: fp32 or fp16 output via overload
__device__ __forceinline__ void store2(float* p, float a, float b) {
    *(float2*)p = make_float2(a, b);
}
__device__ __forceinline__ void store2(__half* p, float a, float b) {
    *(__half2*)p = __floats2half2_rn(a, b);
}

// ---------------- fp16 mma.sync GEMM: C[M,N] = A[M,K] @ W[N,K]^T + bias[N] ---
// BM=BN=128, BK=64, 256 threads (8 warps 2x4), warp tile 64x32 (4x4 m16n8k16).
// fp32 accumulate; OutT = float or __half. Row stride 72 halves (144B) keeps
// every 8-row ldmatrix phase conflict-free. 3-stage cp.async pipeline, one
// barrier per K-tile; fragment double-buffering across the 4 k16 sub-steps.
#define ROWB 144                          // bytes per smem row (72 halves)
#define TILE_BYTES (128 * ROWB)           // 18432 B per tile (A or B)
#define STG_BYTES (2 * TILE_BYTES)        // 36864 B per stage
#define GEMM_SMEM (3 * STG_BYTES + 512)   // 111104 B

template<typename OutT>
__global__ __launch_bounds__(256, 2) void gemm_mma(
    const __half* __restrict__ A, const __half* __restrict__ W,
    const float* __restrict__ bias, OutT* __restrict__ C,
    int M, int N, int K)
{
    extern __shared__ char smem[];
    float* sBias = (float*)(smem + 3 * STG_BYTES);
    const uint32_t smem_u = (uint32_t)__cvta_generic_to_shared(smem);

    const int tid = threadIdx.x, warp = tid >> 5, lane = tid & 31;
    const int gid = lane >> 2, tig = lane & 3;
    const int bm = blockIdx.y * 128, bn = blockIdx.x * 128;
    const int wm = (warp >> 2) * 64, wn = (warp & 3) * 32;
    const int KT = K / 64;

    if (tid < 128) {
        int c = bn + tid;
        sBias[tid] = (c < N) ? bias[c] : 0.0f;
    }

    float acc[4][4][4];
#pragma unroll
    for (int i = 0; i < 4; i++)
#pragma unroll
        for (int j = 0; j < 4; j++)
#pragma unroll
            for (int r = 0; r < 4; r++) acc[i][j][r] = 0.0f;

    const int lrow = tid >> 3, lc16 = tid & 7;
    auto load_stage = [&](int kt) {
        char* st = smem + (kt % 3) * STG_BYTES;
        const int k0 = kt * 64;
#pragma unroll
        for (int i = 0; i < 4; i++) {
            const int row = lrow + i * 32;
            cp_async16(st + row * ROWB + lc16 * 16,
                       A + (size_t)(bm + row) * K + k0 + lc16 * 8);
            int rB = bn + row; if (rB >= N) rB = N - 1;   // clamp; junk cols never stored
            cp_async16(st + TILE_BYTES + row * ROWB + lc16 * 16,
                       W + (size_t)rB * K + k0 + lc16 * 8);
        }
        cp_commit();
    };

    const uint32_t aOff = (uint32_t)(wm + (lane & 15)) * ROWB + ((lane >> 4) << 4);
    const uint32_t bOff = TILE_BYTES
        + (uint32_t)(wn + ((lane >> 4) << 3) + (lane & 7)) * ROWB + (((lane >> 3) & 1) << 4);

    load_stage(0);
    load_stage(1);

    for (int kt = 0; kt < KT; kt++) {
        if (kt + 1 < KT) cp_wait<1>(); else cp_wait<0>();
        __syncthreads();                       // stage kt visible; stage (kt+2)%3 free
        if (kt + 2 < KT) load_stage(kt + 2);

        const uint32_t stg = smem_u + (kt % 3) * STG_BYTES;
        const uint32_t aB = stg + aOff;
        const uint32_t bB = stg + bOff;

        uint32_t Af[2][4][4], Bq[2][2][4];
#pragma unroll
        for (int i = 0; i < 4; i++) ldsm_x4(aB + (uint32_t)(i * 16 * ROWB), Af[0][i]);
#pragma unroll
        for (int p = 0; p < 2; p++) ldsm_x4(bB + (uint32_t)(p * 16 * ROWB), Bq[0][p]);

#pragma unroll
        for (int kk = 0; kk < 4; kk++) {       // 4 x k16 sub-steps (32B each)
            const int cur = kk & 1;
            if (kk < 3) {   // prefetch kk+1 fragments while cur's MMAs drain
                const uint32_t ko = (uint32_t)(kk + 1) * 32;
#pragma unroll
                for (int i = 0; i < 4; i++)
                    ldsm_x4(aB + ko + (uint32_t)(i * 16 * ROWB), Af[cur ^ 1][i]);
#pragma unroll
                for (int p = 0; p < 2; p++)
                    ldsm_x4(bB + ko + (uint32_t)(p * 16 * ROWB), Bq[cur ^ 1][p]);
            }
#pragma unroll
            for (int i = 0; i < 4; i++)
#pragma unroll
                for (int j = 0; j < 4; j++)
                    mma16816(acc[i][j], Af[cur][i], &Bq[cur][j >> 1][(j & 1) * 2]);
        }
    }

    // epilogue: direct 2-wide stores (+bias)
#pragma unroll
    for (int i = 0; i < 4; i++) {
        const int r0 = bm + wm + i * 16 + gid;
        const int r1 = r0 + 8;
#pragma unroll
        for (int j = 0; j < 4; j++) {
            const int c = wn + j * 8 + tig * 2;
            if (bn + c < N) {
                const float b0 = sBias[c], b1 = sBias[c + 1];
                store2(C + (size_t)r0 * N + bn + c, acc[i][j][0] + b0, acc[i][j][1] + b1);
                store2(C + (size_t)r1 * N + bn + c, acc[i][j][2] + b0, acc[i][j][3] + b1);
            }
        }
    }
}

// ---------------- fp32 -> fp16 rounding prepass (float4 in, 8B out) ----------
__global__ __launch_bounds__(256) void round_fp16_k(
    const float* __restrict__ in, __half* __restrict__ out, int n)
{
    int i = (blockIdx.x * 256 + threadIdx.x) * 4;
    if (i < n) {
        float4 v = *(const float4*)(in + i);
        *(__half2*)(out + i)     = __floats2half2_rn(v.x, v.y);
        *(__half2*)(out + i + 2) = __floats2half2_rn(v.z, v.w);
    }
}

// ---------------- RMSNorm: fp32 in -> fp16 out (R13 version) ----------------
__global__ __launch_bounds__(256) void rmsnorm_fp16(
    const float* __restrict__ data, const float* __restrict__ w,
    __half* __restrict__ outp, int W)
{
    const int t = blockIdx.x, tid = threadIdx.x;
    const float* p = data + (size_t)t * W;
    __half* o = outp + (size_t)t * W;
    const int W4 = W >> 2;
    float ss = 0.f;
    for (int i = tid; i < W4; i += 256) {
        float4 v = ((const float4*)p)[i];
        ss += v.x * v.x + v.y * v.y + v.z * v.z + v.w * v.w;
    }
    __shared__ float red[256];
    red[tid] = ss; __syncthreads();
    for (int w2 = 128; w2 > 0; w2 >>= 1) {
        if (tid < w2) red[tid] += red[tid + w2];
        __syncthreads();
    }
    const float inv = rsqrtf(red[0] / (float)W + 1.1920929e-7f);
    for (int i = tid; i < W4; i += 256) {
        float4 v = ((const float4*)p)[i];
        const float4 g = ((const float4*)w)[i];
        __half2 h0 = __floats2half2_rn(v.x * inv * g.x, v.y * inv * g.y);
        __half2 h1 = __floats2half2_rn(v.z * inv * g.z, v.w * inv * g.w);
        *(__half2*)(o + i * 4) = h0;
        *(__half2*)(o + i * 4 + 2) = h1;
    }
}

// ---------------- kv_a post-process: rmsnorm(512)->fp16 + rope(last 64) ------
__global__ __launch_bounds__(128) void kv_prep(
    const float* __restrict__ kva, const float* __restrict__ knw,
    const float* __restrict__ cosb, const float* __restrict__ sinb,
    __half* __restrict__ kvn, float* __restrict__ kpe, int S)
{
    const int t = blockIdx.x, tid = threadIdx.x;
    const int s = t % S;
    const float* src = kva + (size_t)t * 576;
    float ss = 0.f;
    for (int i = tid; i < 512; i += 128) { float v = src[i]; ss += v * v; }
    __shared__ float red[128];
    red[tid] = ss; __syncthreads();
    for (int w2 = 64; w2 > 0; w2 >>= 1) {
        if (tid < w2) red[tid] += red[tid + w2];
        __syncthreads();
    }
    const float inv = rsqrtf(red[0] / 512.0f + 1.1920929e-7f);
    for (int i = tid; i < 512; i += 128)
        kvn[(size_t)t * 512 + i] = __float2half_rn(src[i] * inv * knw[i]);
    if (tid < 32) {
        const int j = tid;
        const float c = cosb[s * 32 + j], sn = sinb[s * 32 + j];
        const float x0 = src[512 + 2 * j], x1 = src[512 + 2 * j + 1];
        kpe[(size_t)t * 64 + 2 * j]     = x0 * c  - x1 * sn;
        kpe[(size_t)t * 64 + 2 * j + 1] = x0 * sn + x1 * c;
    }
}

// ---------------- per-token attention (fp16 in, fp16 out, fp32 math) ---------
#define ATT_SCALE 0.07216878364870322f  // (128+64)^-0.5
__global__ __launch_bounds__(128) void attn_kernel(
    const __half* __restrict__ q, const __half* __restrict__ kv,
    const float* __restrict__ kpe, const float* __restrict__ cosb,
    const float* __restrict__ sinb, __half* __restrict__ out, int S)
{
    const int t = blockIdx.x, tid = threadIdx.x;
    const int s = t % S;
    __shared__ float qs[3072];
    __shared__ float kvs[16 * 260];
    __shared__ float kp[64];
    __shared__ float sc[16][17];

    const __half* qg = q + (size_t)t * 3072;
    for (int i = tid; i < 1536; i += 128) {
        float2 f = __half22float2(((const __half2*)qg)[i]);
        qs[2 * i] = f.x; qs[2 * i + 1] = f.y;
    }
    const __half* kvg = kv + (size_t)t * 4096;
    for (int i = tid; i < 2048; i += 128) {
        const int g = i >> 7, c = i & 127;
        float2 f = __half22float2(((const __half2*)kvg)[i]);
        kvs[g * 260 + 2 * c] = f.x; kvs[g * 260 + 2 * c + 1] = f.y;
    }
    if (tid < 16) ((float4*)kp)[tid] = ((const float4*)(kpe + (size_t)t * 64))[tid];
    __syncthreads();

    for (int p = tid; p < 512; p += 128) {
        const int h = p >> 5, j = p & 31;
        const float c = cosb[s * 32 + j], sn = sinb[s * 32 + j];
        const int i0 = h * 192 + 128 + 2 * j;
        const float x0 = qs[i0], x1 = qs[i0 + 1];
        qs[i0]     = x0 * c  - x1 * sn;
        qs[i0 + 1] = x0 * sn + x1 * c;
    }
    __syncthreads();

    {
        const int h = tid >> 3, g0 = tid & 7, g1 = g0 + 8;
        const float* qh = &qs[h * 192];
        const float* k0 = &kvs[g0 * 260];
        const float* k1 = &kvs[g1 * 260];
        float a0 = 0.f, a1 = 0.f;
#pragma unroll 8
        for (int d = 0; d < 128; d++) { const float qd = qh[d]; a0 += qd * k0[d]; a1 += qd * k1[d]; }
        float pe = 0.f;
        const float* qp = &qs[h * 192 + 128];
#pragma unroll 8
        for (int d = 0; d < 64; d++) pe += qp[d] * kp[d];
        sc[h][g0] = (a0 + pe) * ATT_SCALE;
        sc[h][g1] = (a1 + pe) * ATT_SCALE;
    }
    __syncthreads();

    if (tid < 16) {
        float m = -1e30f;
#pragma unroll
        for (int g = 0; g < 16; g++) m = fmaxf(m, sc[tid][g]);
        float sum = 0.f;
#pragma unroll
        for (int g = 0; g < 16; g++) { const float e = expf(sc[tid][g] - m); sc[tid][g] = e; sum += e; }
        const float r = 1.f / sum;
#pragma unroll
        for (int g = 0; g < 16; g++) sc[tid][g] *= r;
    }
    __syncthreads();

    for (int o = tid; o < 2048; o += 128) {
        const int h = o >> 7, d = o & 127;
        float acc = 0.f;
#pragma unroll
        for (int g = 0; g < 16; g++) acc += sc[h][g] * kvs[g * 260 + 128 + d];
        out[(size_t)t * 2048 + o] = __float2half_rn(acc);
    }
}

// ---------------- host launcher (R13 dual-stream fork/join, serial tail) -----
template<typename OutT>
static inline void launch_gemm_s(cudaStream_t st, const __half* A, const __half* W,
                                 const float* bias, OutT* C, int M, int N, int K)
{
    dim3 grid((N + 127) / 128, M / 128);
    gemm_mma<OutT><<<grid, 256, GEMM_SMEM, st>>>(A, W, bias, C, M, N, K);
}
static inline void launch_round_s(cudaStream_t st, const float* in, __half* out, int n)
{
    round_fp16_k<<<(n / 4 + 255) / 256, 256, 0, st>>>(in, out, n);
}

extern "C" void kernel_launch(void* const* d_in, const int* in_sizes, int n_in,
                              void* d_out, int out_size)
{
    const float* x     = (const float*)d_in[0];
    const float* fcos  = (const float*)d_in[1];
    const float* fsin  = (const float*)d_in[2];
    const float* wqa   = (const float*)d_in[3];
    const float* wqab  = (const float*)d_in[4];
    const float* qnw   = (const float*)d_in[5];
    const float* wqb   = (const float*)d_in[6];
    const float* wqbb  = (const float*)d_in[7];
    const float* wkva  = (const float*)d_in[8];
    const float* wkvab = (const float*)d_in[9];
    const float* kvnw  = (const float*)d_in[10];
    const float* wkvb  = (const float*)d_in[11];
    const float* wkvbb = (const float*)d_in[12];
    const float* wo    = (const float*)d_in[13];
    const float* wob   = (const float*)d_in[14];
    float* out = (float*)d_out;

    const int T = in_sizes[0] / 2048;   // B*S tokens (8192)
    const int S = in_sizes[1] / 32;     // 2048

    float *qa, *kva, *kpe;
    __half *qah, *qq, *kvn, *kv, *ao, *xh, *wh;
    cudaGetSymbolAddress((void**)&qa,  g_qa);
    cudaGetSymbolAddress((void**)&qah, g_qah);
    cudaGetSymbolAddress((void**)&qq,  g_q);
    cudaGetSymbolAddress((void**)&kva, g_kva);
    cudaGetSymbolAddress((void**)&kvn, g_kvn);
    cudaGetSymbolAddress((void**)&kpe, g_kpe);
    cudaGetSymbolAddress((void**)&kv,  g_kv);
    cudaGetSymbolAddress((void**)&ao,  g_ao);
    cudaGetSymbolAddress((void**)&xh,  g_xh);
    cudaGetSymbolAddress((void**)&wh,  g_wh);

    cudaFuncSetAttribute(gemm_mma<float>,  cudaFuncAttributeMaxDynamicSharedMemorySize, GEMM_SMEM);
    cudaFuncSetAttribute(gemm_mma<__half>, cudaFuncAttributeMaxDynamicSharedMemorySize, GEMM_SMEM);

    // Host-side stream/event handles, created once (uncaptured correctness
    // call); identical DAG recorded on every call -> identical graph.
    static cudaStream_t s1 = nullptr;
    static cudaEvent_t eFork, eX, eWQB, eKV;
    if (s1 == nullptr) {
        cudaStreamCreateWithFlags(&s1, cudaStreamNonBlocking);
        cudaEventCreateWithFlags(&eFork, cudaEventDisableTiming);
        cudaEventCreateWithFlags(&eX,    cudaEventDisableTiming);
        cudaEventCreateWithFlags(&eWQB,  cudaEventDisableTiming);
        cudaEventCreateWithFlags(&eKV,   cudaEventDisableTiming);
    }
    cudaStream_t d = 0;                 // capture-origin (legacy default) stream

    // fork s1 off the capture stream
    cudaEventRecord(eFork, d);
    cudaStreamWaitEvent(s1, eFork, 0);

    // ---- default stream: q path ----
    launch_round_s(d, x, xh, T * 2048);
    cudaEventRecord(eX, d);                               // xh ready
    launch_round_s(d, wqa, wh + WQA_OFF, 1536 * 2048);
    launch_gemm_s(d, xh, wh + WQA_OFF, wqab, qa, T, 1536, 2048);
    rmsnorm_fp16<<<T, 256, 0, d>>>(qa, qnw, qah, 1536);

    // ---- s1: remaining weight rounds + kv path ----
    launch_round_s(s1, wqb, wh + WQB_OFF, 3072 * 1536);
    cudaEventRecord(eWQB, s1);                            // wqb(h) ready
    launch_round_s(s1, wkva, wh + WKVA_OFF, 576 * 2048);
    launch_round_s(s1, wkvb, wh + WKVB_OFF, 4096 * 512);
    launch_round_s(s1, wo,   wh + WO_OFF,   2048 * 2048);
    cudaStreamWaitEvent(s1, eX, 0);                       // needs xh
    launch_gemm_s(s1, xh, wh + WKVA_OFF, wkvab, kva, T, 576, 2048);
    kv_prep<<<T, 128, 0, s1>>>(kva, kvnw, fcos, fsin, kvn, kpe, S);
    launch_gemm_s(s1, kvn, wh + WKVB_OFF, wkvbb, kv, T, 4096, 512);
    cudaEventRecord(eKV, s1);                             // kv path done (incl. wo round)

    // ---- default stream: wq_b, then join and finish ----
    cudaStreamWaitEvent(d, eWQB, 0);
    launch_gemm_s(d, qah, wh + WQB_OFF, wqbb, qq, T, 3072, 1536);
    cudaStreamWaitEvent(d, eKV, 0);                       // join s1
    attn_kernel<<<T, 128, 0, d>>>(qq, kv, kpe, fcos, fsin, ao, S);
    launch_gemm_s(d, ao, wh + WO_OFF, wob, out, T, 2048, 2048);
}

// round 16
// speedup vs baseline: 1.0723x; 1.0723x over previous
#include <cuda_runtime.h>
#include <cuda_fp16.h>
#include <cstdint>

// ---------------- scratch (allocation-free: __device__ globals) ----------------
#define T_TOK 8192
__device__ float  g_qa [T_TOK*1536];   // wq_a output (fp32)
__device__ __half g_qah[T_TOK*1536];   // rmsnorm(qa) in fp16
__device__ __half g_q  [T_TOK*3072];   // wq_b output (fp16, attention input)
__device__ float  g_kva[T_TOK*576];    // wkv_a output (fp32)
__device__ __half g_kvn[T_TOK*512];    // normalized kv latent (fp16)
__device__ float  g_kpe[T_TOK*64];     // roped k_pe
__device__ __half g_kv [T_TOK*4096];   // wkv_b output (fp16)
__device__ __half g_ao [T_TOK*2048];   // attention output (fp16)
__device__ __half g_xh [T_TOK*2048];   // x in fp16
__device__ __half g_wh [15335424];     // all 5 weight matrices in fp16

#define WQA_OFF   0
#define WQB_OFF   3145728
#define WKVA_OFF  7864320
#define WKVB_OFF  9043968
#define WO_OFF    11141120

// ---------------- PTX helpers (arch-generic: sm_80+) ----------------
__device__ __forceinline__ void cp_async16(void* dst, const void* src) {
    unsigned s = (unsigned)__cvta_generic_to_shared(dst);
    asm volatile("cp.async.cg.shared.global [%0], [%1], 16;\n" :: "r"(s), "l"(src));
}
__device__ __forceinline__ void cp_commit() { asm volatile("cp.async.commit_group;\n"); }
template<int N> __device__ __forceinline__ void cp_wait() {
    asm volatile("cp.async.wait_group %0;\n" :: "n"(N));
}
__device__ __forceinline__ void mma16816(float* d, const uint32_t* a, const uint32_t* b) {
    asm volatile(
        "mma.sync.aligned.m16n8k16.row.col.f32.f16.f16.f32 "
        "{%0,%1,%2,%3}, {%4,%5,%6,%7}, {%8,%9}, {%0,%1,%2,%3};"
        : "+f"(d[0]), "+f"(d[1]), "+f"(d[2]), "+f"(d[3])
        : "r"(a[0]), "r"(a[1]), "r"(a[2]), "r"(a[3]), "r"(b[0]), "r"(b[1]));
}
__device__ __forceinline__ void ldsm_x4(uint32_t a, uint32_t* r) {
    asm volatile("ldmatrix.sync.aligned.m8n8.x4.shared.b16 {%0,%1,%2,%3}, [%4];"
        : "=r"(r[0]), "=r"(r[1]), "=r"(r[2]), "=r"(r[3]) : "r"(a));
}
// epilogue store: fp32 or fp16 output via overload
__device__ __forceinline__ void store2(float* p, float a, float b) {
    *(float2*)p = make_float2(a, b);
}
__device__ __forceinline__ void store2(__half* p, float a, float b) {
    *(__half2*)p = __floats2half2_rn(a, b);
}

// ---------------- fp16 mma.sync GEMM: C[M,N] = A[M,K] @ W[N,K]^T + bias[N] ---
// BM=BN=128, BK=64, 256 threads (8 warps 2x4), warp tile 64x32 (4x4 m16n8k16).
// fp32 accumulate; OutT = float or __half. Row stride 72 halves (144B) keeps
// every 8-row ldmatrix phase conflict-free. 3-stage cp.async pipeline, one
// barrier per K-tile; fragment double-buffering across the 4 k16 sub-steps.
#define ROWB 144                          // bytes per smem row (72 halves)
#define TILE_BYTES (128 * ROWB)           // 18432 B per tile (A or B)
#define STG_BYTES (2 * TILE_BYTES)        // 36864 B per stage
#define GEMM_SMEM (3 * STG_BYTES + 512)   // 111104 B

template<typename OutT>
__global__ __launch_bounds__(256, 2) void gemm_mma(
    const __half* __restrict__ A, const __half* __restrict__ W,
    const float* __restrict__ bias, OutT* __restrict__ C,
    int M, int N, int K)
{
    extern __shared__ char smem[];
    float* sBias = (float*)(smem + 3 * STG_BYTES);
    const uint32_t smem_u = (uint32_t)__cvta_generic_to_shared(smem);

    const int tid = threadIdx.x, warp = tid >> 5, lane = tid & 31;
    const int gid = lane >> 2, tig = lane & 3;
    const int bm = blockIdx.y * 128, bn = blockIdx.x * 128;
    const int wm = (warp >> 2) * 64, wn = (warp & 3) * 32;
    const int KT = K / 64;

    if (tid < 128) {
        int c = bn + tid;
        sBias[tid] = (c < N) ? bias[c] : 0.0f;
    }

    float acc[4][4][4];
#pragma unroll
    for (int i = 0; i < 4; i++)
#pragma unroll
        for (int j = 0; j < 4; j++)
#pragma unroll
            for (int r = 0; r < 4; r++) acc[i][j][r] = 0.0f;

    const int lrow = tid >> 3, lc16 = tid & 7;
    auto load_stage = [&](int kt) {
        char* st = smem + (kt % 3) * STG_BYTES;
        const int k0 = kt * 64;
#pragma unroll
        for (int i = 0; i < 4; i++) {
            const int row = lrow + i * 32;
            cp_async16(st + row * ROWB + lc16 * 16,
                       A + (size_t)(bm + row) * K + k0 + lc16 * 8);
            int rB = bn + row; if (rB >= N) rB = N - 1;   // clamp; junk cols never stored
            cp_async16(st + TILE_BYTES + row * ROWB + lc16 * 16,
                       W + (size_t)rB * K + k0 + lc16 * 8);
        }
        cp_commit();
    };

    const uint32_t aOff = (uint32_t)(wm + (lane & 15)) * ROWB + ((lane >> 4) << 4);
    const uint32_t bOff = TILE_BYTES
        + (uint32_t)(wn + ((lane >> 4) << 3) + (lane & 7)) * ROWB + (((lane >> 3) & 1) << 4);

    load_stage(0);
    load_stage(1);

    for (int kt = 0; kt < KT; kt++) {
        if (kt + 1 < KT) cp_wait<1>(); else cp_wait<0>();
        __syncthreads();                       // stage kt visible; stage (kt+2)%3 free
        if (kt + 2 < KT) load_stage(kt + 2);

        const uint32_t stg = smem_u + (kt % 3) * STG_BYTES;
        const uint32_t aB = stg + aOff;
        const uint32_t bB = stg + bOff;

        uint32_t Af[2][4][4], Bq[2][2][4];
#pragma unroll
        for (int i = 0; i < 4; i++) ldsm_x4(aB + (uint32_t)(i * 16 * ROWB), Af[0][i]);
#pragma unroll
        for (int p = 0; p < 2; p++) ldsm_x4(bB + (uint32_t)(p * 16 * ROWB), Bq[0][p]);

#pragma unroll
        for (int kk = 0; kk < 4; kk++) {       // 4 x k16 sub-steps (32B each)
            const int cur = kk & 1;
            if (kk < 3) {   // prefetch kk+1 fragments while cur's MMAs drain
                const uint32_t ko = (uint32_t)(kk + 1) * 32;
#pragma unroll
                for (int i = 0; i < 4; i++)
                    ldsm_x4(aB + ko + (uint32_t)(i * 16 * ROWB), Af[cur ^ 1][i]);
#pragma unroll
                for (int p = 0; p < 2; p++)
                    ldsm_x4(bB + ko + (uint32_t)(p * 16 * ROWB), Bq[cur ^ 1][p]);
            }
#pragma unroll
            for (int i = 0; i < 4; i++)
#pragma unroll
                for (int j = 0; j < 4; j++)
                    mma16816(acc[i][j], Af[cur][i], &Bq[cur][j >> 1][(j & 1) * 2]);
        }
    }

    // epilogue: direct 2-wide stores (+bias)
#pragma unroll
    for (int i = 0; i < 4; i++) {
        const int r0 = bm + wm + i * 16 + gid;
        const int r1 = r0 + 8;
#pragma unroll
        for (int j = 0; j < 4; j++) {
            const int c = wn + j * 8 + tig * 2;
            if (bn + c < N) {
                const float b0 = sBias[c], b1 = sBias[c + 1];
                store2(C + (size_t)r0 * N + bn + c, acc[i][j][0] + b0, acc[i][j][1] + b1);
                store2(C + (size_t)r1 * N + bn + c, acc[i][j][2] + b0, acc[i][j][3] + b1);
            }
        }
    }
}

// ---------------- fp32 -> fp16 rounding prepass (float4 in, 8B out) ----------
__global__ __launch_bounds__(256) void round_fp16_k(
    const float* __restrict__ in, __half* __restrict__ out, int n)
{
    int i = (blockIdx.x * 256 + threadIdx.x) * 4;
    if (i < n) {
        float4 v = *(const float4*)(in + i);
        *(__half2*)(out + i)     = __floats2half2_rn(v.x, v.y);
        *(__half2*)(out + i + 2) = __floats2half2_rn(v.z, v.w);
    }
}

// ---------------- RMSNorm: fp32 in -> fp16 out (R13 version) ----------------
__global__ __launch_bounds__(256) void rmsnorm_fp16(
    const float* __restrict__ data, const float* __restrict__ w,
    __half* __restrict__ outp, int W)
{
    const int t = blockIdx.x, tid = threadIdx.x;
    const float* p = data + (size_t)t * W;
    __half* o = outp + (size_t)t * W;
    const int W4 = W >> 2;
    float ss = 0.f;
    for (int i = tid; i < W4; i += 256) {
        float4 v = ((const float4*)p)[i];
        ss += v.x * v.x + v.y * v.y + v.z * v.z + v.w * v.w;
    }
    __shared__ float red[256];
    red[tid] = ss; __syncthreads();
    for (int w2 = 128; w2 > 0; w2 >>= 1) {
        if (tid < w2) red[tid] += red[tid + w2];
        __syncthreads();
    }
    const float inv = rsqrtf(red[0] / (float)W + 1.1920929e-7f);
    for (int i = tid; i < W4; i += 256) {
        float4 v = ((const float4*)p)[i];
        const float4 g = ((const float4*)w)[i];
        __half2 h0 = __floats2half2_rn(v.x * inv * g.x, v.y * inv * g.y);
        __half2 h1 = __floats2half2_rn(v.z * inv * g.z, v.w * inv * g.w);
        *(__half2*)(o + i * 4) = h0;
        *(__half2*)(o + i * 4 + 2) = h1;
    }
}

// ---------------- kv_a post-process: rmsnorm(512)->fp16 + rope(last 64) ------
__global__ __launch_bounds__(128) void kv_prep(
    const float* __restrict__ kva, const float* __restrict__ knw,
    const float* __restrict__ cosb, const float* __restrict__ sinb,
    __half* __restrict__ kvn, float* __restrict__ kpe, int S)
{
    const int t = blockIdx.x, tid = threadIdx.x;
    const int s = t % S;
    const float* src = kva + (size_t)t * 576;
    float ss = 0.f;
    for (int i = tid; i < 512; i += 128) { float v = src[i]; ss += v * v; }
    __shared__ float red[128];
    red[tid] = ss; __syncthreads();
    for (int w2 = 64; w2 > 0; w2 >>= 1) {
        if (tid < w2) red[tid] += red[tid + w2];
        __syncthreads();
    }
    const float inv = rsqrtf(red[0] / 512.0f + 1.1920929e-7f);
    for (int i = tid; i < 512; i += 128)
        kvn[(size_t)t * 512 + i] = __float2half_rn(src[i] * inv * knw[i]);
    if (tid < 32) {
        const int j = tid;
        const float c = cosb[s * 32 + j], sn = sinb[s * 32 + j];
        const float x0 = src[512 + 2 * j], x1 = src[512 + 2 * j + 1];
        kpe[(size_t)t * 64 + 2 * j]     = x0 * c  - x1 * sn;
        kpe[(size_t)t * 64 + 2 * j + 1] = x0 * sn + x1 * c;
    }
}

// ---------------- per-token attention: fp16 in/out, WIDE (16B) accesses ------
#define ATT_SCALE 0.07216878364870322f  // (128+64)^-0.5
__global__ __launch_bounds__(128) void attn_kernel(
    const __half* __restrict__ q, const __half* __restrict__ kv,
    const float* __restrict__ kpe, const float* __restrict__ cosb,
    const float* __restrict__ sinb, __half* __restrict__ out, int S)
{
    const int t = blockIdx.x, tid = threadIdx.x;
    const int s = t % S;
    __shared__ float qs[3072];
    __shared__ float kvs[16 * 260];
    __shared__ float kp[64];
    __shared__ float sc[16][17];

    // q: 3072 halves = 384 float4-chunks (8 halves each), 3 per thread
    const float4* qg4 = (const float4*)(q + (size_t)t * 3072);
    for (int i = tid; i < 384; i += 128) {
        float4 raw = qg4[i];
        const __half2* hp = (const __half2*)&raw;
#pragma unroll
        for (int u = 0; u < 4; u++) {
            float2 f = __half22float2(hp[u]);
            qs[8 * i + 2 * u]     = f.x;
            qs[8 * i + 2 * u + 1] = f.y;
        }
    }
    // kv: 4096 halves = 512 float4-chunks; group g = i>>5 (32 chunks = 256 halves)
    const float4* kvg4 = (const float4*)(kv + (size_t)t * 4096);
    for (int i = tid; i < 512; i += 128) {
        const int g = i >> 5, c = i & 31;
        float4 raw = kvg4[i];
        const __half2* hp = (const __half2*)&raw;
        float* dst = &kvs[g * 260 + c * 8];
#pragma unroll
        for (int u = 0; u < 4; u++) {
            float2 f = __half22float2(hp[u]);
            dst[2 * u]     = f.x;
            dst[2 * u + 1] = f.y;
        }
    }
    if (tid < 16) ((float4*)kp)[tid] = ((const float4*)(kpe + (size_t)t * 64))[tid];
    __syncthreads();

    for (int p = tid; p < 512; p += 128) {
        const int h = p >> 5, j = p & 31;
        const float c = cosb[s * 32 + j], sn = sinb[s * 32 + j];
        const int i0 = h * 192 + 128 + 2 * j;
        const float x0 = qs[i0], x1 = qs[i0 + 1];
        qs[i0]     = x0 * c  - x1 * sn;
        qs[i0 + 1] = x0 * sn + x1 * c;
    }
    __syncthreads();

    {
        const int h = tid >> 3, g0 = tid & 7, g1 = g0 + 8;
        const float* qh = &qs[h * 192];
        const float* k0 = &kvs[g0 * 260];
        const float* k1 = &kvs[g1 * 260];
        float a0 = 0.f, a1 = 0.f;
#pragma unroll 8
        for (int d = 0; d < 128; d++) { const float qd = qh[d]; a0 += qd * k0[d]; a1 += qd * k1[d]; }
        float pe = 0.f;
        const float* qp = &qs[h * 192 + 128];
#pragma unroll 8
        for (int d = 0; d < 64; d++) pe += qp[d] * kp[d];
        sc[h][g0] = (a0 + pe) * ATT_SCALE;
        sc[h][g1] = (a1 + pe) * ATT_SCALE;
    }
    __syncthreads();

    if (tid < 16) {
        float m = -1e30f;
#pragma unroll
        for (int g = 0; g < 16; g++) m = fmaxf(m, sc[tid][g]);
        float sum = 0.f;
#pragma unroll
        for (int g = 0; g < 16; g++) { const float e = expf(sc[tid][g] - m); sc[tid][g] = e; sum += e; }
        const float r = 1.f / sum;
#pragma unroll
        for (int g = 0; g < 16; g++) sc[tid][g] *= r;
    }
    __syncthreads();

    // output: 2 halves per thread-step -> 4B __half2 stores
    for (int o = tid * 2; o < 2048; o += 256) {
        const int h = o >> 7, d = o & 127;
        float a0 = 0.f, a1 = 0.f;
#pragma unroll
        for (int g = 0; g < 16; g++) {
            const float w = sc[h][g];
            a0 += w * kvs[g * 260 + 128 + d];
            a1 += w * kvs[g * 260 + 128 + d + 1];
        }
        *(__half2*)(out + (size_t)t * 2048 + o) = __floats2half2_rn(a0, a1);
    }
}

// ---------------- host launcher (R13 dual-stream fork/join, serial tail) -----
template<typename OutT>
static inline void launch_gemm_s(cudaStream_t st, const __half* A, const __half* W,
                                 const float* bias, OutT* C, int M, int N, int K)
{
    dim3 grid((N + 127) / 128, M / 128);
    gemm_mma<OutT><<<grid, 256, GEMM_SMEM, st>>>(A, W, bias, C, M, N, K);
}
static inline void launch_round_s(cudaStream_t st, const float* in, __half* out, int n)
{
    round_fp16_k<<<(n / 4 + 255) / 256, 256, 0, st>>>(in, out, n);
}

extern "C" void kernel_launch(void* const* d_in, const int* in_sizes, int n_in,
                              void* d_out, int out_size)
{
    const float* x     = (const float*)d_in[0];
    const float* fcos  = (const float*)d_in[1];
    const float* fsin  = (const float*)d_in[2];
    const float* wqa   = (const float*)d_in[3];
    const float* wqab  = (const float*)d_in[4];
    const float* qnw   = (const float*)d_in[5];
    const float* wqb   = (const float*)d_in[6];
    const float* wqbb  = (const float*)d_in[7];
    const float* wkva  = (const float*)d_in[8];
    const float* wkvab = (const float*)d_in[9];
    const float* kvnw  = (const float*)d_in[10];
    const float* wkvb  = (const float*)d_in[11];
    const float* wkvbb = (const float*)d_in[12];
    const float* wo    = (const float*)d_in[13];
    const float* wob   = (const float*)d_in[14];
    float* out = (float*)d_out;

    const int T = in_sizes[0] / 2048;   // B*S tokens (8192)
    const int S = in_sizes[1] / 32;     // 2048

    float *qa, *kva, *kpe;
    __half *qah, *qq, *kvn, *kv, *ao, *xh, *wh;
    cudaGetSymbolAddress((void**)&qa,  g_qa);
    cudaGetSymbolAddress((void**)&qah, g_qah);
    cudaGetSymbolAddress((void**)&qq,  g_q);
    cudaGetSymbolAddress((void**)&kva, g_kva);
    cudaGetSymbolAddress((void**)&kvn, g_kvn);
    cudaGetSymbolAddress((void**)&kpe, g_kpe);
    cudaGetSymbolAddress((void**)&kv,  g_kv);
    cudaGetSymbolAddress((void**)&ao,  g_ao);
    cudaGetSymbolAddress((void**)&xh,  g_xh);
    cudaGetSymbolAddress((void**)&wh,  g_wh);

    cudaFuncSetAttribute(gemm_mma<float>,  cudaFuncAttributeMaxDynamicSharedMemorySize, GEMM_SMEM);
    cudaFuncSetAttribute(gemm_mma<__half>, cudaFuncAttributeMaxDynamicSharedMemorySize, GEMM_SMEM);

    // Host-side stream/event handles, created once (uncaptured correctness
    // call); identical DAG recorded on every call -> identical graph.
    static cudaStream_t s1 = nullptr;
    static cudaEvent_t eFork, eX, eWQB, eKV;
    if (s1 == nullptr) {
        cudaStreamCreateWithFlags(&s1, cudaStreamNonBlocking);
        cudaEventCreateWithFlags(&eFork, cudaEventDisableTiming);
        cudaEventCreateWithFlags(&eX,    cudaEventDisableTiming);
        cudaEventCreateWithFlags(&eWQB,  cudaEventDisableTiming);
        cudaEventCreateWithFlags(&eKV,   cudaEventDisableTiming);
    }
    cudaStream_t d = 0;                 // capture-origin (legacy default) stream

    // fork s1 off the capture stream
    cudaEventRecord(eFork, d);
    cudaStreamWaitEvent(s1, eFork, 0);

    // ---- default stream: q path ----
    launch_round_s(d, x, xh, T * 2048);
    cudaEventRecord(eX, d);                               // xh ready
    launch_round_s(d, wqa, wh + WQA_OFF, 1536 * 2048);
    launch_gemm_s(d, xh, wh + WQA_OFF, wqab, qa, T, 1536, 2048);
    rmsnorm_fp16<<<T, 256, 0, d>>>(qa, qnw, qah, 1536);

    // ---- s1: remaining weight rounds + kv path ----
    launch_round_s(s1, wqb, wh + WQB_OFF, 3072 * 1536);
    cudaEventRecord(eWQB, s1);                            // wqb(h) ready
    launch_round_s(s1, wkva, wh + WKVA_OFF, 576 * 2048);
    launch_round_s(s1, wkvb, wh + WKVB_OFF, 4096 * 512);
    launch_round_s(s1, wo,   wh + WO_OFF,   2048 * 2048);
    cudaStreamWaitEvent(s1, eX, 0);                       // needs xh
    launch_gemm_s(s1, xh, wh + WKVA_OFF, wkvab, kva, T, 576, 2048);
    kv_prep<<<T, 128, 0, s1>>>(kva, kvnw, fcos, fsin, kvn, kpe, S);
    launch_gemm_s(s1, kvn, wh + WKVB_OFF, wkvbb, kv, T, 4096, 512);
    cudaEventRecord(eKV, s1);                             // kv path done (incl. wo round)

    // ---- default stream: wq_b, then join and finish ----
    cudaStreamWaitEvent(d, eWQB, 0);
    launch_gemm_s(d, qah, wh + WQB_OFF, wqbb, qq, T, 3072, 1536);
    cudaStreamWaitEvent(d, eKV, 0);                       // join s1
    attn_kernel<<<T, 128, 0, d>>>(qq, kv, kpe, fcos, fsin, ao, S);
    launch_gemm_s(d, ao, wh + WO_OFF, wob, out, T, 2048, 2048);
}

// round 17
// speedup vs baseline: 1.0799x; 1.0070x over previous
#include <cuda_runtime.h>
#include <cuda_fp16.h>
#include <cstdint>

// ---------------- scratch (allocation-free: __device__ globals) ----------------
#define T_TOK 8192
__device__ __half g_qa [T_TOK*1536];   // wq_a output (fp16)
__device__ __half g_qah[T_TOK*1536];   // rmsnorm(qa) in fp16
__device__ __half g_q  [T_TOK*3072];   // wq_b output (fp16, attention input)
__device__ float  g_kva[T_TOK*576];    // wkv_a output (fp32)
__device__ __half g_kvn[T_TOK*512];    // normalized kv latent (fp16)
__device__ float  g_kpe[T_TOK*64];     // roped k_pe
__device__ __half g_kv [T_TOK*4096];   // wkv_b output (fp16)
__device__ __half g_ao [T_TOK*2048];   // attention output (fp16)
__device__ __half g_xh [T_TOK*2048];   // x in fp16
__device__ __half g_wh [15335424];     // all 5 weight matrices in fp16

#define WQA_OFF   0
#define WQB_OFF   3145728
#define WKVA_OFF  7864320
#define WKVB_OFF  9043968
#define WO_OFF    11141120

// ---------------- PTX helpers (arch-generic: sm_80+) ----------------
__device__ __forceinline__ void cp_async16(void* dst, const void* src) {
    unsigned s = (unsigned)__cvta_generic_to_shared(dst);
    asm volatile("cp.async.cg.shared.global [%0], [%1], 16;\n" :: "r"(s), "l"(src));
}
__device__ __forceinline__ void cp_commit() { asm volatile("cp.async.commit_group;\n"); }
template<int N> __device__ __forceinline__ void cp_wait() {
    asm volatile("cp.async.wait_group %0;\n" :: "n"(N));
}
__device__ __forceinline__ void mma16816(float* d, const uint32_t* a, const uint32_t* b) {
    asm volatile(
        "mma.sync.aligned.m16n8k16.row.col.f32.f16.f16.f32 "
        "{%0,%1,%2,%3}, {%4,%5,%6,%7}, {%8,%9}, {%0,%1,%2,%3};"
        : "+f"(d[0]), "+f"(d[1]), "+f"(d[2]), "+f"(d[3])
        : "r"(a[0]), "r"(a[1]), "r"(a[2]), "r"(a[3]), "r"(b[0]), "r"(b[1]));
}
__device__ __forceinline__ void ldsm_x4(uint32_t a, uint32_t* r) {
    asm volatile("ldmatrix.sync.aligned.m8n8.x4.shared.b16 {%0,%1,%2,%3}, [%4];"
        : "=r"(r[0]), "=r"(r[1]), "=r"(r[2]), "=r"(r[3]) : "r"(a));
}
// epilogue store: fp32 or fp16 output via overload
__device__ __forceinline__ void store2(float* p, float a, float b) {
    *(float2*)p = make_float2(a, b);
}
__device__ __forceinline__ void store2(__half* p, float a, float b) {
    *(__half2*)p = __floats2half2_rn(a, b);
}

// ---------------- fp16 mma.sync GEMM: C[M,N] = A[M,K] @ W[N,K]^T + bias[N] ---
// BM=BN=128, BK=64, 256 threads (8 warps 2x4), warp tile 64x32 (4x4 m16n8k16).
// fp32 accumulate; OutT = float or __half. Row stride 72 halves (144B) keeps
// every 8-row ldmatrix phase conflict-free. 3-stage cp.async pipeline, one
// barrier per K-tile; fragment double-buffering across the 4 k16 sub-steps.
#define ROWB 144                          // bytes per smem row (72 halves)
#define TILE_BYTES (128 * ROWB)           // 18432 B per tile (A or B)
#define STG_BYTES (2 * TILE_BYTES)        // 36864 B per stage
#define GEMM_SMEM (3 * STG_BYTES + 512)   // 111104 B

template<typename OutT>
__global__ __launch_bounds__(256, 2) void gemm_mma(
    const __half* __restrict__ A, const __half* __restrict__ W,
    const float* __restrict__ bias, OutT* __restrict__ C,
    int M, int N, int K)
{
    extern __shared__ char smem[];
    float* sBias = (float*)(smem + 3 * STG_BYTES);
    const uint32_t smem_u = (uint32_t)__cvta_generic_to_shared(smem);

    const int tid = threadIdx.x, warp = tid >> 5, lane = tid & 31;
    const int gid = lane >> 2, tig = lane & 3;
    const int bm = blockIdx.y * 128, bn = blockIdx.x * 128;
    const int wm = (warp >> 2) * 64, wn = (warp & 3) * 32;
    const int KT = K / 64;

    if (tid < 128) {
        int c = bn + tid;
        sBias[tid] = (c < N) ? bias[c] : 0.0f;
    }

    float acc[4][4][4];
#pragma unroll
    for (int i = 0; i < 4; i++)
#pragma unroll
        for (int j = 0; j < 4; j++)
#pragma unroll
            for (int r = 0; r < 4; r++) acc[i][j][r] = 0.0f;

    const int lrow = tid >> 3, lc16 = tid & 7;
    auto load_stage = [&](int kt) {
        char* st = smem + (kt % 3) * STG_BYTES;
        const int k0 = kt * 64;
#pragma unroll
        for (int i = 0; i < 4; i++) {
            const int row = lrow + i * 32;
            cp_async16(st + row * ROWB + lc16 * 16,
                       A + (size_t)(bm + row) * K + k0 + lc16 * 8);
            int rB = bn + row; if (rB >= N) rB = N - 1;   // clamp; junk cols never stored
            cp_async16(st + TILE_BYTES + row * ROWB + lc16 * 16,
                       W + (size_t)rB * K + k0 + lc16 * 8);
        }
        cp_commit();
    };

    const uint32_t aOff = (uint32_t)(wm + (lane & 15)) * ROWB + ((lane >> 4) << 4);
    const uint32_t bOff = TILE_BYTES
        + (uint32_t)(wn + ((lane >> 4) << 3) + (lane & 7)) * ROWB + (((lane >> 3) & 1) << 4);

    load_stage(0);
    load_stage(1);

    for (int kt = 0; kt < KT; kt++) {
        if (kt + 1 < KT) cp_wait<1>(); else cp_wait<0>();
        __syncthreads();                       // stage kt visible; stage (kt+2)%3 free
        if (kt + 2 < KT) load_stage(kt + 2);

        const uint32_t stg = smem_u + (kt % 3) * STG_BYTES;
        const uint32_t aB = stg + aOff;
        const uint32_t bB = stg + bOff;

        uint32_t Af[2][4][4], Bq[2][2][4];
#pragma unroll
        for (int i = 0; i < 4; i++) ldsm_x4(aB + (uint32_t)(i * 16 * ROWB), Af[0][i]);
#pragma unroll
        for (int p = 0; p < 2; p++) ldsm_x4(bB + (uint32_t)(p * 16 * ROWB), Bq[0][p]);

#pragma unroll
        for (int kk = 0; kk < 4; kk++) {       // 4 x k16 sub-steps (32B each)
            const int cur = kk & 1;
            if (kk < 3) {   // prefetch kk+1 fragments while cur's MMAs drain
                const uint32_t ko = (uint32_t)(kk + 1) * 32;
#pragma unroll
                for (int i = 0; i < 4; i++)
                    ldsm_x4(aB + ko + (uint32_t)(i * 16 * ROWB), Af[cur ^ 1][i]);
#pragma unroll
                for (int p = 0; p < 2; p++)
                    ldsm_x4(bB + ko + (uint32_t)(p * 16 * ROWB), Bq[cur ^ 1][p]);
            }
#pragma unroll
            for (int i = 0; i < 4; i++)
#pragma unroll
                for (int j = 0; j < 4; j++)
                    mma16816(acc[i][j], Af[cur][i], &Bq[cur][j >> 1][(j & 1) * 2]);
        }
    }

    // epilogue: direct 2-wide stores (+bias)
#pragma unroll
    for (int i = 0; i < 4; i++) {
        const int r0 = bm + wm + i * 16 + gid;
        const int r1 = r0 + 8;
#pragma unroll
        for (int j = 0; j < 4; j++) {
            const int c = wn + j * 8 + tig * 2;
            if (bn + c < N) {
                const float b0 = sBias[c], b1 = sBias[c + 1];
                store2(C + (size_t)r0 * N + bn + c, acc[i][j][0] + b0, acc[i][j][1] + b1);
                store2(C + (size_t)r1 * N + bn + c, acc[i][j][2] + b0, acc[i][j][3] + b1);
            }
        }
    }
}

// ---------------- fp32 -> fp16 rounding prepass (float4 in, 8B out) ----------
__global__ __launch_bounds__(256) void round_fp16_k(
    const float* __restrict__ in, __half* __restrict__ out, int n)
{
    int i = (blockIdx.x * 256 + threadIdx.x) * 4;
    if (i < n) {
        float4 v = *(const float4*)(in + i);
        *(__half2*)(out + i)     = __floats2half2_rn(v.x, v.y);
        *(__half2*)(out + i + 2) = __floats2half2_rn(v.z, v.w);
    }
}

// ---------------- RMSNorm: fp16 in (WIDE float4 loads) -> fp16 out ----------
__global__ __launch_bounds__(256) void rmsnorm_fp16(
    const __half* __restrict__ data, const float* __restrict__ w,
    __half* __restrict__ outp, int W)
{
    const int t = blockIdx.x, tid = threadIdx.x;
    const __half* p = data + (size_t)t * W;
    __half* o = outp + (size_t)t * W;
    const int W8 = W >> 3;                 // float4 chunks of 8 halves
    float ss = 0.f;
    float vbuf[8];                          // W=1536 -> 192 chunks; <=1 per thread
    {
        const int i = tid;                  // 192 < 256: one chunk per thread
        if (i < W8) {
            float4 raw = ((const float4*)p)[i];
            const __half2* hp = (const __half2*)&raw;
#pragma unroll
            for (int u = 0; u < 4; u++) {
                float2 f = __half22float2(hp[u]);
                vbuf[2 * u] = f.x; vbuf[2 * u + 1] = f.y;
                ss += f.x * f.x + f.y * f.y;
            }
        }
    }
    __shared__ float red[256];
    red[tid] = ss; __syncthreads();
    for (int w2 = 128; w2 > 0; w2 >>= 1) {
        if (tid < w2) red[tid] += red[tid + w2];
        __syncthreads();
    }
    const float inv = rsqrtf(red[0] / (float)W + 1.1920929e-7f);
    if (tid < W8) {
        const float4 g0 = ((const float4*)w)[2 * tid];
        const float4 g1 = ((const float4*)w)[2 * tid + 1];
        const float gs[8] = {g0.x, g0.y, g0.z, g0.w, g1.x, g1.y, g1.z, g1.w};
        float4 raw;
        __half2* hp = (__half2*)&raw;
#pragma unroll
        for (int u = 0; u < 4; u++)
            hp[u] = __floats2half2_rn(vbuf[2 * u] * inv * gs[2 * u],
                                      vbuf[2 * u + 1] * inv * gs[2 * u + 1]);
        ((float4*)o)[tid] = raw;
    }
}

// ---------------- kv_a post-process: rmsnorm(512)->fp16 + rope(last 64) ------
__global__ __launch_bounds__(128) void kv_prep(
    const float* __restrict__ kva, const float* __restrict__ knw,
    const float* __restrict__ cosb, const float* __restrict__ sinb,
    __half* __restrict__ kvn, float* __restrict__ kpe, int S)
{
    const int t = blockIdx.x, tid = threadIdx.x;
    const int s = t % S;
    const float* src = kva + (size_t)t * 576;
    float ss = 0.f;
    for (int i = tid; i < 512; i += 128) { float v = src[i]; ss += v * v; }
    __shared__ float red[128];
    red[tid] = ss; __syncthreads();
    for (int w2 = 64; w2 > 0; w2 >>= 1) {
        if (tid < w2) red[tid] += red[tid + w2];
        __syncthreads();
    }
    const float inv = rsqrtf(red[0] / 512.0f + 1.1920929e-7f);
    for (int i = tid; i < 512; i += 128)
        kvn[(size_t)t * 512 + i] = __float2half_rn(src[i] * inv * knw[i]);
    if (tid < 32) {
        const int j = tid;
        const float c = cosb[s * 32 + j], sn = sinb[s * 32 + j];
        const float x0 = src[512 + 2 * j], x1 = src[512 + 2 * j + 1];
        kpe[(size_t)t * 64 + 2 * j]     = x0 * c  - x1 * sn;
        kpe[(size_t)t * 64 + 2 * j + 1] = x0 * sn + x1 * c;
    }
}

// ---------------- per-token attention: fp16 in/out, WIDE (16B) accesses ------
#define ATT_SCALE 0.07216878364870322f  // (128+64)^-0.5
__global__ __launch_bounds__(128) void attn_kernel(
    const __half* __restrict__ q, const __half* __restrict__ kv,
    const float* __restrict__ kpe, const float* __restrict__ cosb,
    const float* __restrict__ sinb, __half* __restrict__ out, int S)
{
    const int t = blockIdx.x, tid = threadIdx.x;
    const int s = t % S;
    __shared__ float qs[3072];
    __shared__ float kvs[16 * 260];
    __shared__ float kp[64];
    __shared__ float sc[16][17];

    // q: 3072 halves = 384 float4-chunks (8 halves each), 3 per thread
    const float4* qg4 = (const float4*)(q + (size_t)t * 3072);
    for (int i = tid; i < 384; i += 128) {
        float4 raw = qg4[i];
        const __half2* hp = (const __half2*)&raw;
#pragma unroll
        for (int u = 0; u < 4; u++) {
            float2 f = __half22float2(hp[u]);
            qs[8 * i + 2 * u]     = f.x;
            qs[8 * i + 2 * u + 1] = f.y;
        }
    }
    // kv: 4096 halves = 512 float4-chunks; group g = i>>5 (32 chunks = 256 halves)
    const float4* kvg4 = (const float4*)(kv + (size_t)t * 4096);
    for (int i = tid; i < 512; i += 128) {
        const int g = i >> 5, c = i & 31;
        float4 raw = kvg4[i];
        const __half2* hp = (const __half2*)&raw;
        float* dst = &kvs[g * 260 + c * 8];
#pragma unroll
        for (int u = 0; u < 4; u++) {
            float2 f = __half22float2(hp[u]);
            dst[2 * u]     = f.x;
            dst[2 * u + 1] = f.y;
        }
    }
    if (tid < 16) ((float4*)kp)[tid] = ((const float4*)(kpe + (size_t)t * 64))[tid];
    __syncthreads();

    for (int p = tid; p < 512; p += 128) {
        const int h = p >> 5, j = p & 31;
        const float c = cosb[s * 32 + j], sn = sinb[s * 32 + j];
        const int i0 = h * 192 + 128 + 2 * j;
        const float x0 = qs[i0], x1 = qs[i0 + 1];
        qs[i0]     = x0 * c  - x1 * sn;
        qs[i0 + 1] = x0 * sn + x1 * c;
    }
    __syncthreads();

    {
        const int h = tid >> 3, g0 = tid & 7, g1 = g0 + 8;
        const float* qh = &qs[h * 192];
        const float* k0 = &kvs[g0 * 260];
        const float* k1 = &kvs[g1 * 260];
        float a0 = 0.f, a1 = 0.f;
#pragma unroll 8
        for (int d = 0; d < 128; d++) { const float qd = qh[d]; a0 += qd * k0[d]; a1 += qd * k1[d]; }
        float pe = 0.f;
        const float* qp = &qs[h * 192 + 128];
#pragma unroll 8
        for (int d = 0; d < 64; d++) pe += qp[d] * kp[d];
        sc[h][g0] = (a0 + pe) * ATT_SCALE;
        sc[h][g1] = (a1 + pe) * ATT_SCALE;
    }
    __syncthreads();

    if (tid < 16) {
        float m = -1e30f;
#pragma unroll
        for (int g = 0; g < 16; g++) m = fmaxf(m, sc[tid][g]);
        float sum = 0.f;
#pragma unroll
        for (int g = 0; g < 16; g++) { const float e = expf(sc[tid][g] - m); sc[tid][g] = e; sum += e; }
        const float r = 1.f / sum;
#pragma unroll
        for (int g = 0; g < 16; g++) sc[tid][g] *= r;
    }
    __syncthreads();

    // output: 2 halves per thread-step -> 4B __half2 stores
    for (int o = tid * 2; o < 2048; o += 256) {
        const int h = o >> 7, d = o & 127;
        float a0 = 0.f, a1 = 0.f;
#pragma unroll
        for (int g = 0; g < 16; g++) {
            const float w = sc[h][g];
            a0 += w * kvs[g * 260 + 128 + d];
            a1 += w * kvs[g * 260 + 128 + d + 1];
        }
        *(__half2*)(out + (size_t)t * 2048 + o) = __floats2half2_rn(a0, a1);
    }
}

// ---------------- host launcher (dual-stream fork/join, serial tail) ---------
template<typename OutT>
static inline void launch_gemm_s(cudaStream_t st, const __half* A, const __half* W,
                                 const float* bias, OutT* C, int M, int N, int K)
{
    dim3 grid((N + 127) / 128, M / 128);
    gemm_mma<OutT><<<grid, 256, GEMM_SMEM, st>>>(A, W, bias, C, M, N, K);
}
static inline void launch_round_s(cudaStream_t st, const float* in, __half* out, int n)
{
    round_fp16_k<<<(n / 4 + 255) / 256, 256, 0, st>>>(in, out, n);
}

extern "C" void kernel_launch(void* const* d_in, const int* in_sizes, int n_in,
                              void* d_out, int out_size)
{
    const float* x     = (const float*)d_in[0];
    const float* fcos  = (const float*)d_in[1];
    const float* fsin  = (const float*)d_in[2];
    const float* wqa   = (const float*)d_in[3];
    const float* wqab  = (const float*)d_in[4];
    const float* qnw   = (const float*)d_in[5];
    const float* wqb   = (const float*)d_in[6];
    const float* wqbb  = (const float*)d_in[7];
    const float* wkva  = (const float*)d_in[8];
    const float* wkvab = (const float*)d_in[9];
    const float* kvnw  = (const float*)d_in[10];
    const float* wkvb  = (const float*)d_in[11];
    const float* wkvbb = (const float*)d_in[12];
    const float* wo    = (const float*)d_in[13];
    const float* wob   = (const float*)d_in[14];
    float* out = (float*)d_out;

    const int T = in_sizes[0] / 2048;   // B*S tokens (8192)
    const int S = in_sizes[1] / 32;     // 2048

    float *kva, *kpe;
    __half *qa, *qah, *qq, *kvn, *kv, *ao, *xh, *wh;
    cudaGetSymbolAddress((void**)&qa,  g_qa);
    cudaGetSymbolAddress((void**)&qah, g_qah);
    cudaGetSymbolAddress((void**)&qq,  g_q);
    cudaGetSymbolAddress((void**)&kva, g_kva);
    cudaGetSymbolAddress((void**)&kvn, g_kvn);
    cudaGetSymbolAddress((void**)&kpe, g_kpe);
    cudaGetSymbolAddress((void**)&kv,  g_kv);
    cudaGetSymbolAddress((void**)&ao,  g_ao);
    cudaGetSymbolAddress((void**)&xh,  g_xh);
    cudaGetSymbolAddress((void**)&wh,  g_wh);

    cudaFuncSetAttribute(gemm_mma<float>,  cudaFuncAttributeMaxDynamicSharedMemorySize, GEMM_SMEM);
    cudaFuncSetAttribute(gemm_mma<__half>, cudaFuncAttributeMaxDynamicSharedMemorySize, GEMM_SMEM);

    // Host-side stream/event handles, created once (uncaptured correctness
    // call); identical DAG recorded on every call -> identical graph.
    static cudaStream_t s1 = nullptr;
    static cudaEvent_t eFork, eX, eWQA, eWQB, eKV;
    if (s1 == nullptr) {
        cudaStreamCreateWithFlags(&s1, cudaStreamNonBlocking);
        cudaEventCreateWithFlags(&eFork, cudaEventDisableTiming);
        cudaEventCreateWithFlags(&eX,    cudaEventDisableTiming);
        cudaEventCreateWithFlags(&eWQA,  cudaEventDisableTiming);
        cudaEventCreateWithFlags(&eWQB,  cudaEventDisableTiming);
        cudaEventCreateWithFlags(&eKV,   cudaEventDisableTiming);
    }
    cudaStream_t d = 0;                 // capture-origin (legacy default) stream

    // fork s1 off the capture stream
    cudaEventRecord(eFork, d);
    cudaStreamWaitEvent(s1, eFork, 0);

    // ---- s1 head: round wqa (concurrent with round_x on d) ----
    launch_round_s(s1, wqa, wh + WQA_OFF, 1536 * 2048);
    cudaEventRecord(eWQA, s1);

    // ---- default stream: q path ----
    launch_round_s(d, x, xh, T * 2048);
    cudaEventRecord(eX, d);                               // xh ready
    cudaStreamWaitEvent(d, eWQA, 0);                      // wqa(h) ready
    launch_gemm_s(d, xh, wh + WQA_OFF, wqab, qa, T, 1536, 2048);
    rmsnorm_fp16<<<T, 256, 0, d>>>(qa, qnw, qah, 1536);

    // ---- s1: remaining weight rounds + kv path ----
    launch_round_s(s1, wqb, wh + WQB_OFF, 3072 * 1536);
    cudaEventRecord(eWQB, s1);                            // wqb(h) ready
    launch_round_s(s1, wkva, wh + WKVA_OFF, 576 * 2048);
    launch_round_s(s1, wkvb, wh + WKVB_OFF, 4096 * 512);
    launch_round_s(s1, wo,   wh + WO_OFF,   2048 * 2048);
    cudaStreamWaitEvent(s1, eX, 0);                       // needs xh
    launch_gemm_s(s1, xh, wh + WKVA_OFF, wkvab, kva, T, 576, 2048);
    kv_prep<<<T, 128, 0, s1>>>(kva, kvnw, fcos, fsin, kvn, kpe, S);
    launch_gemm_s(s1, kvn, wh + WKVB_OFF, wkvbb, kv, T, 4096, 512);
    cudaEventRecord(eKV, s1);                             // kv path done (incl. wo round)

    // ---- default stream: wq_b, then join and finish ----
    cudaStreamWaitEvent(d, eWQB, 0);
    launch_gemm_s(d, qah, wh + WQB_OFF, wqbb, qq, T, 3072, 1536);
    cudaStreamWaitEvent(d, eKV, 0);                       // join s1
    attn_kernel<<<T, 128, 0, d>>>(qq, kv, kpe, fcos, fsin, ao, S);
    launch_gemm_s(d, ao, wh + WO_OFF, wob, out, T, 2048, 2048);
}